// round 4
// baseline (speedup 1.0000x reference)
#include <cuda_runtime.h>
#include <cuda_bf16.h>
#include <cstdint>
#include <math.h>

// Shapes: text[256,512] f32, clip[256,512] f32, concept[256,32,512] f32,
// frame[256,64,512] f32, logit_scale scalar, out[256,256] f32.
// Big GEMM S[8192,16384] = nc @ nf^T in FP8 e4m3 (x16 pre-scale, /256 post),
// f32 acc, fused max-over-64-frames / mean-over-32-tokens epilogue.
// g_sim precomputed fp32 by warp-dot blocks. compute_103 target: mma.sync only.

#define D_K     512
#define A_ROWS  8192
#define B_ROWS  16384
#define NCH     4             // 512 / 128 k-chunks (128 fp8 = 128 B per row)
#define MT      64            // 8192 / 128
#define NT      128           // 16384 / 128
#define AIMG    16384         // 128 rows * 128 B
#define BIMG    16384
#define STAGE   32768
#define NSTAGES 3
#define SMEM_DYN (NSTAGES * STAGE)
#define PREP_BLOCKS 3072      // (A_ROWS+B_ROWS)/8
#define GSIM_BLOCKS 256       // 2048 warps: warp = (1 token, 32 videos)

// Packed, pre-swizzled e4m3 operand images:
//   g_ncp: [chunk(4)][mtile(64)][16384 B], g_nfp: [chunk(4)][ntile(128)][16384 B]
__device__ __align__(256) unsigned char g_ncp[(size_t)NCH * MT * AIMG];
__device__ __align__(256) unsigned char g_nfp[(size_t)NCH * NT * BIMG];
__device__ __align__(256) float g_gsim[256 * 256];

// ---------------------------------------------------------------------------
__device__ __forceinline__ uint32_t smem_u32(const void* p) {
    uint32_t a;
    asm("{ .reg .u64 t; cvta.to.shared.u64 t, %1; cvt.u32.u64 %0, t; }"
        : "=r"(a) : "l"(p));
    return a;
}
__device__ __forceinline__ void cp_async16(uint32_t dst, const void* src) {
    asm volatile("cp.async.cg.shared.global [%0], [%1], 16;"
                 :: "r"(dst), "l"(src) : "memory");
}
__device__ __forceinline__ void cp_commit() {
    asm volatile("cp.async.commit_group;" ::: "memory");
}
template <int N>
__device__ __forceinline__ void cp_wait() {
    asm volatile("cp.async.wait_group %0;" :: "n"(N) : "memory");
}
__device__ __forceinline__ void ldm_x4(uint32_t* r, uint32_t addr) {
    asm volatile("ldmatrix.sync.aligned.m8n8.x4.shared.b16 {%0,%1,%2,%3}, [%4];"
                 : "=r"(r[0]), "=r"(r[1]), "=r"(r[2]), "=r"(r[3]) : "r"(addr));
}
// fp8 e4m3 MMA: m16n8k32, fragment layout == bf16 m16n8k16 with 4 fp8/reg-slot
__device__ __forceinline__ void mma16832(float* c, const uint32_t* a,
                                         uint32_t b0, uint32_t b1) {
    asm volatile(
        "mma.sync.aligned.m16n8k32.row.col.f32.e4m3.e4m3.f32 "
        "{%0,%1,%2,%3}, {%4,%5,%6,%7}, {%8,%9}, {%0,%1,%2,%3};"
        : "+f"(c[0]), "+f"(c[1]), "+f"(c[2]), "+f"(c[3])
        : "r"(a[0]), "r"(a[1]), "r"(a[2]), "r"(a[3]), "r"(b0), "r"(b1));
}
__device__ __forceinline__ uint16_t cvt_e4m3x2(float hi, float lo) {
    uint16_t r;
    asm("cvt.rn.satfinite.e4m3x2.f32 %0, %1, %2;" : "=h"(r) : "f"(hi), "f"(lo));
    return r;
}

// ---------------------------------------------------------------------------
// Kernel 1 (fused):
//   blocks [0, 3072): L2-normalize, x16, -> e4m3 swizzled packed images.
//   blocks [3072, 3328): fp32 g_sim = text @ clip^T, warp-dot (1 token x 32 v).
// ---------------------------------------------------------------------------
__global__ __launch_bounds__(256) void prep_kernel(
    const float* __restrict__ text, const float* __restrict__ clip,
    const float* __restrict__ concept_e, const float* __restrict__ frame_e) {
    int wid = threadIdx.x >> 5;
    int lane = threadIdx.x & 31;

    if (blockIdx.x >= PREP_BLOCKS) {
        // ---- g_sim warp-dot ----
        int gw = (blockIdx.x - PREP_BLOCKS) * 8 + wid;   // 0..2047
        int t = gw >> 3;
        int vbase = (gw & 7) * 32;

        float4 tv[4];
        const float4* tr = (const float4*)(text + (size_t)t * D_K);
#pragma unroll
        for (int j = 0; j < 4; j++) tv[j] = tr[lane * 4 + j];

#pragma unroll 1
        for (int vi = 0; vi < 32; vi++) {
            int v = vbase + vi;
            const float4* cr = (const float4*)(clip + (size_t)v * D_K);
            float g = 0.f;
#pragma unroll
            for (int j = 0; j < 4; j++) {
                float4 cv = cr[lane * 4 + j];
                g += tv[j].x * cv.x + tv[j].y * cv.y + tv[j].z * cv.z + tv[j].w * cv.w;
            }
#pragma unroll
            for (int off = 16; off > 0; off >>= 1)
                g += __shfl_xor_sync(0xffffffffu, g, off);
            if (lane == 0) g_gsim[(size_t)t * 256 + v] = g;
        }
        return;
    }

    // ---- normalize + x16 + e4m3 + swizzled pack ----
    int R = blockIdx.x * 8 + wid;               // 0 .. 24575

    const float* src;
    unsigned char* img;
    size_t chunk_stride;
    int rowin;
    if (R < A_ROWS) {
        src = concept_e + (size_t)R * D_K;
        img = g_ncp + (size_t)(R >> 7) * AIMG;
        rowin = R & 127;
        chunk_stride = (size_t)MT * AIMG;
    } else {
        int Rf = R - A_ROWS;
        src = frame_e + (size_t)Rf * D_K;
        img = g_nfp + (size_t)(Rf >> 7) * BIMG;
        rowin = Rf & 127;
        chunk_stride = (size_t)NT * BIMG;
    }

    float4 v[4];
    const float4* s4 = (const float4*)src;
#pragma unroll
    for (int i = 0; i < 4; i++) v[i] = s4[lane * 4 + i];

    float ss = 0.f;
#pragma unroll
    for (int i = 0; i < 4; i++)
        ss += v[i].x * v[i].x + v[i].y * v[i].y + v[i].z * v[i].z + v[i].w * v[i].w;
#pragma unroll
    for (int off = 16; off > 0; off >>= 1)
        ss += __shfl_xor_sync(0xffffffffu, ss, off);

    // x16 pre-scale keeps all e4m3 values in the normal range
    float inv = 16.0f / fmaxf(sqrtf(ss), 1e-12f);

    float f[16] = { v[0].x, v[0].y, v[0].z, v[0].w, v[1].x, v[1].y, v[1].z, v[1].w,
                    v[2].x, v[2].y, v[2].z, v[2].w, v[3].x, v[3].y, v[3].z, v[3].w };
    uint32_t w32[4];
#pragma unroll
    for (int j = 0; j < 4; j++) {
        uint16_t lo = cvt_e4m3x2(f[4 * j + 1] * inv, f[4 * j + 0] * inv);
        uint16_t hi = cvt_e4m3x2(f[4 * j + 3] * inv, f[4 * j + 2] * inv);
        w32[j] = (uint32_t)lo | ((uint32_t)hi << 16);
    }

    int kin = lane * 16;                         // byte == element index
    int chunk = kin >> 7;
    int off = rowin * 128 + (kin & 127);
    int swz = off ^ ((off >> 3) & 0x70);
    *(uint4*)(img + (size_t)chunk * chunk_stride + swz) =
        make_uint4(w32[0], w32[1], w32[2], w32[3]);
}

// ---------------------------------------------------------------------------
// Kernel 2: FP8 HMMA GEMM (128x128 tile, K=512), 3-stage cp.async pipeline,
// one barrier per chunk, prefetch-before-MMA; fused max/mean epilogue.
// 8 warps = 4M x 2N; warp tile 32x64; warp == (1 token, 1 video).
// ---------------------------------------------------------------------------
__global__ void __launch_bounds__(256, 2) gemm_kernel(
    const float* __restrict__ lsc, float* __restrict__ out) {
    extern __shared__ unsigned char smem[];
    uint32_t sbase = smem_u32(smem);

    int tid = threadIdx.x, wid = tid >> 5, lane = tid & 31;
    int mtile = blockIdx.y, ntile = blockIdx.x;
    int wm = wid >> 1, wn = wid & 1;

    const unsigned char* asrc = g_ncp + (size_t)mtile * AIMG;
    const unsigned char* bsrc = g_nfp + (size_t)ntile * BIMG;
    const size_t ACS = (size_t)MT * AIMG;
    const size_t BCS = (size_t)NT * BIMG;

    // per-lane ldmatrix addresses (swizzle folded in); byte-identical to the
    // verified bf16 mapping, reinterpreted as fp8 (4 fp8 per 32-bit slot).
    uint32_t Aoff[2], Axm[2];
#pragma unroll
    for (int mt = 0; mt < 2; mt++) {
        int row = wm * 32 + mt * 16 + (lane & 15);
        Aoff[mt] = row * 128;
        Axm[mt] = (row & 7) << 4;
    }
    uint32_t kA = (lane & 16);

    uint32_t Boff[4], Bxm[4];
#pragma unroll
    for (int bp = 0; bp < 4; bp++) {
        int row = wn * 64 + bp * 16 + (lane & 7) + ((lane & 16) ? 8 : 0);
        Boff[bp] = row * 128;
        Bxm[bp] = (row & 7) << 4;
    }
    uint32_t kB = (lane & 8) ? 16u : 0u;

    float acc[2][8][4];
#pragma unroll
    for (int i = 0; i < 2; i++)
#pragma unroll
        for (int j = 0; j < 8; j++)
#pragma unroll
            for (int k = 0; k < 4; k++) acc[i][j][k] = 0.f;

    // prologue: prefetch chunks 0,1
#pragma unroll
    for (int c = 0; c < 2; c++) {
        uint32_t dst = sbase + c * STAGE;
#pragma unroll
        for (int j = 0; j < 8; j++) {
            uint32_t off = tid * 16 + j * 4096;
            const unsigned char* src = (j < 4)
                ? asrc + c * ACS + off
                : bsrc + c * BCS + (off - AIMG);
            cp_async16(dst + off, src);
        }
        cp_commit();
    }

#pragma unroll 1
    for (int c = 0; c < NCH; c++) {
        if (c < NCH - 1) cp_wait<1>(); else cp_wait<0>();
        __syncthreads();
        if (c + 2 < NCH) {
            int cn = c + 2;
            uint32_t dst = sbase + (cn % NSTAGES) * STAGE;
#pragma unroll
            for (int j = 0; j < 8; j++) {
                uint32_t off = tid * 16 + j * 4096;
                const unsigned char* src = (j < 4)
                    ? asrc + cn * ACS + off
                    : bsrc + cn * BCS + (off - AIMG);
                cp_async16(dst + off, src);
            }
            cp_commit();
        }

        uint32_t sa = sbase + (c % NSTAGES) * STAGE;
        uint32_t sb = sa + AIMG;

#pragma unroll
        for (int ks = 0; ks < 4; ks++) {
            uint32_t kb = ks * 32;               // 32 bytes = k32 fp8 window
            uint32_t a[2][4], b[4][4];
#pragma unroll
            for (int mt = 0; mt < 2; mt++)
                ldm_x4(a[mt], sa + Aoff[mt] + ((kb + kA) ^ Axm[mt]));
#pragma unroll
            for (int bp = 0; bp < 4; bp++)
                ldm_x4(b[bp], sb + Boff[bp] + ((kb + kB) ^ Bxm[bp]));
#pragma unroll
            for (int mt = 0; mt < 2; mt++)
#pragma unroll
                for (int bp = 0; bp < 4; bp++) {
                    mma16832(acc[mt][2 * bp],     a[mt], b[bp][0], b[bp][1]);
                    mma16832(acc[mt][2 * bp + 1], a[mt], b[bp][2], b[bp][3]);
                }
        }
    }

    // ---- fused epilogue: per-row max over 64 frame cols, then mean over q ----
    float rm[2][2];
#pragma unroll
    for (int mt = 0; mt < 2; mt++)
#pragma unroll
        for (int h = 0; h < 2; h++) {
            float m = -3.4e38f;
#pragma unroll
            for (int nt = 0; nt < 8; nt++)
                m = fmaxf(m, fmaxf(acc[mt][nt][2 * h], acc[mt][nt][2 * h + 1]));
            rm[mt][h] = m;
        }
#pragma unroll
    for (int off = 1; off <= 2; off <<= 1) {
#pragma unroll
        for (int mt = 0; mt < 2; mt++)
#pragma unroll
            for (int h = 0; h < 2; h++)
                rm[mt][h] = fmaxf(rm[mt][h],
                                  __shfl_xor_sync(0xffffffffu, rm[mt][h], off));
    }
    float s = rm[0][0] + rm[0][1] + rm[1][0] + rm[1][1];
#pragma unroll
    for (int off = 4; off <= 16; off <<= 1)
        s += __shfl_xor_sync(0xffffffffu, s, off);

    if (lane == 0) {
        int t = mtile * 4 + wm;
        int v = ntile * 2 + wn;
        float g = __ldg(&g_gsim[(size_t)t * 256 + v]);
        float scale = fminf(expf(lsc[0]), 100.0f);
        // s is sum of 32 row-maxes of (16*nc)·(16*nf) -> /32 mean, /256 unscale
        out[(size_t)t * 256 + v] =
            scale * (0.7f * g + 0.3f * (s * (1.0f / (32.0f * 256.0f))));
    }
}

// ---------------------------------------------------------------------------
extern "C" void kernel_launch(void* const* d_in, const int* in_sizes, int n_in,
                              void* d_out, int out_size) {
    const float* text    = (const float*)d_in[0];
    const float* clip    = (const float*)d_in[1];
    const float* concept = (const float*)d_in[2];
    const float* frame   = (const float*)d_in[3];
    const float* lsc     = (const float*)d_in[4];
    float* out = (float*)d_out;

    prep_kernel<<<PREP_BLOCKS + GSIM_BLOCKS, 256>>>(text, clip, concept, frame);

    cudaFuncSetAttribute(gemm_kernel, cudaFuncAttributeMaxDynamicSharedMemorySize,
                         SMEM_DYN);
    gemm_kernel<<<dim3(NT, MT), 256, SMEM_DYN>>>(lsc, out);
}

// round 5
// speedup vs baseline: 1.1460x; 1.1460x over previous
#include <cuda_runtime.h>
#include <cuda_fp16.h>
#include <cstdint>
#include <math.h>

// Shapes: text[256,512] f32, clip[256,512] f32, concept[256,32,512] f32,
// frame[256,64,512] f32, logit_scale scalar, out[256,256] f32.
// Big GEMM S[8192,16384] = nc @ nf^T in f16 (f16 acc) with fused
// max-over-64-frames / mean-over-32-tokens epilogue; fp32 g_sim via
// smem-tiled warp blocks. compute_103 target: mma.sync only (no tcgen05).

#define D_K     512
#define A_ROWS  8192
#define B_ROWS  16384
#define NCH     8             // 512 / 64 k-chunks (64 f16 = 128 B per row)
#define MT      64            // 8192 / 128
#define NT      128           // 16384 / 128
#define AIMG    16384         // 128 rows * 128 B
#define BIMG    16384
#define STAGE   32768
#define NSTAGES 2
#define SMEM_DYN (NSTAGES * STAGE)   // 64 KB -> 3 CTAs/SM
#define GSIM_BLOCKS 256       // 32 token-groups x 8 video-groups
#define PREP_BLOCKS 3072      // (A_ROWS+B_ROWS)/8
#define GSIM_SMEM 65536       // 32 videos x 512 f32

// Packed, pre-swizzled f16 operand images:
//   g_ncp: [chunk(8)][mtile(64)][16384 B], g_nfp: [chunk(8)][ntile(128)][16384 B]
__device__ __align__(256) unsigned char g_ncp[(size_t)NCH * MT * AIMG];
__device__ __align__(256) unsigned char g_nfp[(size_t)NCH * NT * BIMG];
__device__ __align__(256) float g_gsim[256 * 256];

// ---------------------------------------------------------------------------
__device__ __forceinline__ uint32_t smem_u32(const void* p) {
    uint32_t a;
    asm("{ .reg .u64 t; cvta.to.shared.u64 t, %1; cvt.u32.u64 %0, t; }"
        : "=r"(a) : "l"(p));
    return a;
}
__device__ __forceinline__ void cp_async16(uint32_t dst, const void* src) {
    asm volatile("cp.async.cg.shared.global [%0], [%1], 16;"
                 :: "r"(dst), "l"(src) : "memory");
}
__device__ __forceinline__ void cp_commit() {
    asm volatile("cp.async.commit_group;" ::: "memory");
}
template <int N>
__device__ __forceinline__ void cp_wait() {
    asm volatile("cp.async.wait_group %0;" :: "n"(N) : "memory");
}
__device__ __forceinline__ void ldm_x4(uint32_t* r, uint32_t addr) {
    asm volatile("ldmatrix.sync.aligned.m8n8.x4.shared.b16 {%0,%1,%2,%3}, [%4];"
                 : "=r"(r[0]), "=r"(r[1]), "=r"(r[2]), "=r"(r[3]) : "r"(addr));
}
// f16 x f16 -> f16 accumulate: 2 C regs (half2 each), same (row,col) map as f32.
__device__ __forceinline__ void mma16816h(uint32_t* c, const uint32_t* a,
                                          uint32_t b0, uint32_t b1) {
    asm volatile(
        "mma.sync.aligned.m16n8k16.row.col.f16.f16.f16.f16 "
        "{%0,%1}, {%2,%3,%4,%5}, {%6,%7}, {%0,%1};"
        : "+r"(c[0]), "+r"(c[1])
        : "r"(a[0]), "r"(a[1]), "r"(a[2]), "r"(a[3]), "r"(b0), "r"(b1));
}

// ---------------------------------------------------------------------------
// Kernel 1 (fused), gsim blocks FIRST so they overlap the normalize blocks:
//   blocks [0, 256): fp32 g_sim tile 8 tokens x 32 videos via smem clip tile.
//   blocks [256, 3328): L2-normalize -> f16 swizzled packed images.
// ---------------------------------------------------------------------------
__global__ __launch_bounds__(256) void prep_kernel(
    const float* __restrict__ text, const float* __restrict__ clip,
    const float* __restrict__ concept_e, const float* __restrict__ frame_e) {
    extern __shared__ float4 csh[];            // [32 videos][128 float4]
    int wid = threadIdx.x >> 5;
    int lane = threadIdx.x & 31;

    if (blockIdx.x < GSIM_BLOCKS) {
        int b = blockIdx.x;
        int tb = (b >> 3) * 8, vb = (b & 7) * 32;

        // load clip tile [32][512] f32 -> smem (coalesced)
        const float4* c4 = (const float4*)(clip + (size_t)vb * D_K);
#pragma unroll
        for (int i = 0; i < 16; i++)
            csh[threadIdx.x + i * 256] = c4[threadIdx.x + i * 256];
        __syncthreads();

        // warp = one token; lane keeps 16 text floats
        int t = tb + wid;
        float4 tv[4];
        const float4* tr = (const float4*)(text + (size_t)t * D_K);
#pragma unroll
        for (int j = 0; j < 4; j++) tv[j] = tr[lane * 4 + j];

        float acc[32];
#pragma unroll 1
        for (int v = 0; v < 32; v++) {
            const float4* cr = csh + v * 128;
            float g = 0.f;
#pragma unroll
            for (int j = 0; j < 4; j++) {
                float4 cv = cr[lane * 4 + j];
                g += tv[j].x * cv.x + tv[j].y * cv.y + tv[j].z * cv.z + tv[j].w * cv.w;
            }
            acc[v] = g;
        }
        // butterfly transpose-reduce: lane v ends holding sum over lanes of acc[v]
#pragma unroll
        for (int off = 16; off > 0; off >>= 1) {
#pragma unroll
            for (int v = 0; v < off; v++) {
                float lo = acc[v], hi = acc[v + off];
                float sent = (lane & off) ? lo : hi;
                float recv = __shfl_xor_sync(0xffffffffu, sent, off);
                acc[v] = ((lane & off) ? hi : lo) + recv;
            }
        }
        g_gsim[(size_t)t * 256 + vb + lane] = acc[0];
        return;
    }

    // ---- normalize + f16 + swizzled pack ----
    int R = (blockIdx.x - GSIM_BLOCKS) * 8 + wid;   // 0 .. 24575

    const float* src;
    unsigned char* img;
    size_t chunk_stride;
    int rowin;
    if (R < A_ROWS) {
        src = concept_e + (size_t)R * D_K;
        img = g_ncp + (size_t)(R >> 7) * AIMG;
        rowin = R & 127;
        chunk_stride = (size_t)MT * AIMG;
    } else {
        int Rf = R - A_ROWS;
        src = frame_e + (size_t)Rf * D_K;
        img = g_nfp + (size_t)(Rf >> 7) * BIMG;
        rowin = Rf & 127;
        chunk_stride = (size_t)NT * BIMG;
    }

    float4 v[4];
    const float4* s4 = (const float4*)src;
#pragma unroll
    for (int i = 0; i < 4; i++) v[i] = s4[lane * 4 + i];

    float ss = 0.f;
#pragma unroll
    for (int i = 0; i < 4; i++)
        ss += v[i].x * v[i].x + v[i].y * v[i].y + v[i].z * v[i].z + v[i].w * v[i].w;
#pragma unroll
    for (int off = 16; off > 0; off >>= 1)
        ss += __shfl_xor_sync(0xffffffffu, ss, off);

    float inv = 1.0f / fmaxf(sqrtf(ss), 1e-12f);

    union { __half2 h[8]; uint4 q[2]; } u;
#pragma unroll
    for (int i = 0; i < 4; i++) {
        u.h[2 * i]     = __float22half2_rn(make_float2(v[i].x * inv, v[i].y * inv));
        u.h[2 * i + 1] = __float22half2_rn(make_float2(v[i].z * inv, v[i].w * inv));
    }

    int kbase = lane * 16;
#pragma unroll
    for (int uu = 0; uu < 2; uu++) {
        int kin = kbase + uu * 8;
        int chunk = kin >> 6;
        int off = rowin * 128 + (kin & 63) * 2;
        int swz = off ^ ((off >> 3) & 0x70);
        *(uint4*)(img + (size_t)chunk * chunk_stride + swz) = u.q[uu];
    }
}

// ---------------------------------------------------------------------------
// Kernel 2: f16 HMMA GEMM (128x128 tile, K=512), 2-stage cp.async ring,
// one barrier per chunk, 3 CTAs/SM; fused max/mean epilogue.
// 8 warps = 4M x 2N; warp tile 32x64; warp == (1 token, 1 video).
// ---------------------------------------------------------------------------
__global__ void __launch_bounds__(256, 3) gemm_kernel(
    const float* __restrict__ lsc, float* __restrict__ out) {
    extern __shared__ unsigned char smem[];
    uint32_t sbase = smem_u32(smem);

    int tid = threadIdx.x, wid = tid >> 5, lane = tid & 31;
    int mtile = blockIdx.y, ntile = blockIdx.x;
    int wm = wid >> 1, wn = wid & 1;

    const unsigned char* asrc = g_ncp + (size_t)mtile * AIMG;
    const unsigned char* bsrc = g_nfp + (size_t)ntile * BIMG;
    const size_t ACS = (size_t)MT * AIMG;
    const size_t BCS = (size_t)NT * BIMG;

    // per-lane ldmatrix addresses (swizzle folded in)
    uint32_t Aoff[2], Axm[2];
#pragma unroll
    for (int mt = 0; mt < 2; mt++) {
        int row = wm * 32 + mt * 16 + (lane & 15);
        Aoff[mt] = row * 128;
        Axm[mt] = (row & 7) << 4;
    }
    uint32_t kA = (lane & 16);

    uint32_t Boff[4], Bxm[4];
#pragma unroll
    for (int bp = 0; bp < 4; bp++) {
        int row = wn * 64 + bp * 16 + (lane & 7) + ((lane & 16) ? 8 : 0);
        Boff[bp] = row * 128;
        Bxm[bp] = (row & 7) << 4;
    }
    uint32_t kB = (lane & 8) ? 16u : 0u;

    uint32_t acc[2][8][2];                 // f16 acc: half2 per reg
#pragma unroll
    for (int i = 0; i < 2; i++)
#pragma unroll
        for (int j = 0; j < 8; j++) { acc[i][j][0] = 0u; acc[i][j][1] = 0u; }

    // prologue: prefetch chunk 0
    {
        uint32_t dst = sbase;
#pragma unroll
        for (int j = 0; j < 8; j++) {
            uint32_t off = tid * 16 + j * 4096;
            const unsigned char* src = (j < 4) ? asrc + off
                                               : bsrc + (off - AIMG);
            cp_async16(dst + off, src);
        }
        cp_commit();
    }

#pragma unroll 1
    for (int c = 0; c < NCH; c++) {
        cp_wait<0>();
        __syncthreads();
        // barrier proves all warps finished chunk c-1 -> its stage is free.
        if (c + 1 < NCH) {
            int cn = c + 1;
            uint32_t dst = sbase + (cn & 1) * STAGE;
#pragma unroll
            for (int j = 0; j < 8; j++) {
                uint32_t off = tid * 16 + j * 4096;
                const unsigned char* src = (j < 4)
                    ? asrc + cn * ACS + off
                    : bsrc + cn * BCS + (off - AIMG);
                cp_async16(dst + off, src);
            }
            cp_commit();
        }

        uint32_t sa = sbase + (c & 1) * STAGE;
        uint32_t sb = sa + AIMG;

#pragma unroll
        for (int ks = 0; ks < 4; ks++) {
            uint32_t kb = ks * 32;
            uint32_t a[2][4], b[4][4];
#pragma unroll
            for (int mt = 0; mt < 2; mt++)
                ldm_x4(a[mt], sa + Aoff[mt] + ((kb + kA) ^ Axm[mt]));
#pragma unroll
            for (int bp = 0; bp < 4; bp++)
                ldm_x4(b[bp], sb + Boff[bp] + ((kb + kB) ^ Bxm[bp]));
#pragma unroll
            for (int mt = 0; mt < 2; mt++)
#pragma unroll
                for (int bp = 0; bp < 4; bp++) {
                    mma16816h(acc[mt][2 * bp],     a[mt], b[bp][0], b[bp][1]);
                    mma16816h(acc[mt][2 * bp + 1], a[mt], b[bp][2], b[bp][3]);
                }
        }
    }

    // ---- fused epilogue: per-row max over 64 frame cols, then mean over q ----
    // acc[mt][nt][h]: half2 = (col even, col odd) for row group h (rows +8h).
    float rm[2][2];
#pragma unroll
    for (int mt = 0; mt < 2; mt++)
#pragma unroll
        for (int h = 0; h < 2; h++) {
            __half2 m = __halves2half2(__ushort_as_half(0xFBFFu),
                                       __ushort_as_half(0xFBFFu));  // -65504
#pragma unroll
            for (int nt = 0; nt < 8; nt++)
                m = __hmax2(m, *(__half2*)&acc[mt][nt][h]);
            float2 f = __half22float2(m);
            rm[mt][h] = fmaxf(f.x, f.y);
        }
#pragma unroll
    for (int off = 1; off <= 2; off <<= 1) {
#pragma unroll
        for (int mt = 0; mt < 2; mt++)
#pragma unroll
            for (int h = 0; h < 2; h++)
                rm[mt][h] = fmaxf(rm[mt][h],
                                  __shfl_xor_sync(0xffffffffu, rm[mt][h], off));
    }
    float s = rm[0][0] + rm[0][1] + rm[1][0] + rm[1][1];
#pragma unroll
    for (int off = 4; off <= 16; off <<= 1)
        s += __shfl_xor_sync(0xffffffffu, s, off);

    if (lane == 0) {
        int t = mtile * 4 + wm;
        int v = ntile * 2 + wn;
        float g = __ldg(&g_gsim[(size_t)t * 256 + v]);
        float scale = fminf(expf(lsc[0]), 100.0f);
        out[(size_t)t * 256 + v] = scale * (0.7f * g + 0.3f * (s * (1.0f / 32.0f)));
    }
}

// ---------------------------------------------------------------------------
extern "C" void kernel_launch(void* const* d_in, const int* in_sizes, int n_in,
                              void* d_out, int out_size) {
    const float* text    = (const float*)d_in[0];
    const float* clip    = (const float*)d_in[1];
    const float* concept = (const float*)d_in[2];
    const float* frame   = (const float*)d_in[3];
    const float* lsc     = (const float*)d_in[4];
    float* out = (float*)d_out;

    cudaFuncSetAttribute(prep_kernel, cudaFuncAttributeMaxDynamicSharedMemorySize,
                         GSIM_SMEM);
    prep_kernel<<<PREP_BLOCKS + GSIM_BLOCKS, 256, GSIM_SMEM>>>(
        text, clip, concept, frame);

    cudaFuncSetAttribute(gemm_kernel, cudaFuncAttributeMaxDynamicSharedMemorySize,
                         SMEM_DYN);
    gemm_kernel<<<dim3(NT, MT), 256, SMEM_DYN>>>(lsc, out);
}

// round 6
// speedup vs baseline: 1.1862x; 1.0351x over previous
#include <cuda_runtime.h>
#include <cuda_fp16.h>
#include <cstdint>
#include <math.h>

// Shapes: text[256,512] f32, clip[256,512] f32, concept[256,32,512] f32,
// frame[256,64,512] f32, logit_scale scalar, out[256,256] f32.
// Big GEMM S[8192,16384] = nc @ nf^T in f16 (f16 acc), fused
// max-over-64-frames / mean-over-32-tokens epilogue; fp32 g_sim precomputed.
// compute_103 target: mma.sync only (no tcgen05).
// CTA tile 128x256, warp tile 64x64 (8 warps = 2M x 4N) -> 8 ldsm / 32 MMA.

#define D_K     512
#define A_ROWS  8192
#define B_ROWS  16384
#define NCH     8             // 512 / 64 k-chunks (64 f16 = 128 B per row)
#define MT      64            // 8192 / 128
#define NT      128           // 16384 / 128 (image count; CTA eats 2)
#define AIMG    16384         // 128 rows * 128 B
#define BIMG    16384
#define STAGE   49152         // 16 KB A + 32 KB B
#define SMEM_DYN (2 * STAGE)  // 96 KB -> 2 CTAs/SM
#define GSIM_BLOCKS 256
#define PREP_BLOCKS 3072
#define GSIM_SMEM 65536

// Packed, pre-swizzled f16 operand images:
//   g_ncp: [chunk(8)][mtile(64)][16384 B], g_nfp: [chunk(8)][ntile(128)][16384 B]
__device__ __align__(256) unsigned char g_ncp[(size_t)NCH * MT * AIMG];
__device__ __align__(256) unsigned char g_nfp[(size_t)NCH * NT * BIMG];
__device__ __align__(256) float g_gsim[256 * 256];

// ---------------------------------------------------------------------------
__device__ __forceinline__ uint32_t smem_u32(const void* p) {
    uint32_t a;
    asm("{ .reg .u64 t; cvta.to.shared.u64 t, %1; cvt.u32.u64 %0, t; }"
        : "=r"(a) : "l"(p));
    return a;
}
__device__ __forceinline__ void cp_async16(uint32_t dst, const void* src) {
    asm volatile("cp.async.cg.shared.global [%0], [%1], 16;"
                 :: "r"(dst), "l"(src) : "memory");
}
__device__ __forceinline__ void cp_commit() {
    asm volatile("cp.async.commit_group;" ::: "memory");
}
template <int N>
__device__ __forceinline__ void cp_wait() {
    asm volatile("cp.async.wait_group %0;" :: "n"(N) : "memory");
}
__device__ __forceinline__ void ldm_x4(uint32_t* r, uint32_t addr) {
    asm volatile("ldmatrix.sync.aligned.m8n8.x4.shared.b16 {%0,%1,%2,%3}, [%4];"
                 : "=r"(r[0]), "=r"(r[1]), "=r"(r[2]), "=r"(r[3]) : "r"(addr));
}
// f16 x f16 -> f16 accumulate: 2 C regs (half2 each)
__device__ __forceinline__ void mma16816h(uint32_t* c, const uint32_t* a,
                                          uint32_t b0, uint32_t b1) {
    asm volatile(
        "mma.sync.aligned.m16n8k16.row.col.f16.f16.f16.f16 "
        "{%0,%1}, {%2,%3,%4,%5}, {%6,%7}, {%0,%1};"
        : "+r"(c[0]), "+r"(c[1])
        : "r"(a[0]), "r"(a[1]), "r"(a[2]), "r"(a[3]), "r"(b0), "r"(b1));
}

// ---------------------------------------------------------------------------
// Kernel 1 (fused), gsim blocks first:
//   blocks [0, 256): fp32 g_sim tile 8 tokens x 32 videos via smem clip tile.
//   blocks [256, 3328): L2-normalize -> f16 swizzled packed images.
// ---------------------------------------------------------------------------
__global__ __launch_bounds__(256) void prep_kernel(
    const float* __restrict__ text, const float* __restrict__ clip,
    const float* __restrict__ concept_e, const float* __restrict__ frame_e) {
    extern __shared__ float4 csh[];            // [32 videos][128 float4]
    int wid = threadIdx.x >> 5;
    int lane = threadIdx.x & 31;

    if (blockIdx.x < GSIM_BLOCKS) {
        int b = blockIdx.x;
        int tb = (b >> 3) * 8, vb = (b & 7) * 32;

        const float4* c4 = (const float4*)(clip + (size_t)vb * D_K);
#pragma unroll
        for (int i = 0; i < 16; i++)
            csh[threadIdx.x + i * 256] = c4[threadIdx.x + i * 256];
        __syncthreads();

        int t = tb + wid;
        float4 tv[4];
        const float4* tr = (const float4*)(text + (size_t)t * D_K);
#pragma unroll
        for (int j = 0; j < 4; j++) tv[j] = tr[lane * 4 + j];

        float acc[32];
#pragma unroll 1
        for (int v = 0; v < 32; v++) {
            const float4* cr = csh + v * 128;
            float g = 0.f;
#pragma unroll
            for (int j = 0; j < 4; j++) {
                float4 cv = cr[lane * 4 + j];
                g += tv[j].x * cv.x + tv[j].y * cv.y + tv[j].z * cv.z + tv[j].w * cv.w;
            }
            acc[v] = g;
        }
#pragma unroll
        for (int off = 16; off > 0; off >>= 1) {
#pragma unroll
            for (int v = 0; v < off; v++) {
                float lo = acc[v], hi = acc[v + off];
                float sent = (lane & off) ? lo : hi;
                float recv = __shfl_xor_sync(0xffffffffu, sent, off);
                acc[v] = ((lane & off) ? hi : lo) + recv;
            }
        }
        g_gsim[(size_t)t * 256 + vb + lane] = acc[0];
        return;
    }

    // ---- normalize + f16 + swizzled pack ----
    int R = (blockIdx.x - GSIM_BLOCKS) * 8 + wid;   // 0 .. 24575

    const float* src;
    unsigned char* img;
    size_t chunk_stride;
    int rowin;
    if (R < A_ROWS) {
        src = concept_e + (size_t)R * D_K;
        img = g_ncp + (size_t)(R >> 7) * AIMG;
        rowin = R & 127;
        chunk_stride = (size_t)MT * AIMG;
    } else {
        int Rf = R - A_ROWS;
        src = frame_e + (size_t)Rf * D_K;
        img = g_nfp + (size_t)(Rf >> 7) * BIMG;
        rowin = Rf & 127;
        chunk_stride = (size_t)NT * BIMG;
    }

    float4 v[4];
    const float4* s4 = (const float4*)src;
#pragma unroll
    for (int i = 0; i < 4; i++) v[i] = s4[lane * 4 + i];

    float ss = 0.f;
#pragma unroll
    for (int i = 0; i < 4; i++)
        ss += v[i].x * v[i].x + v[i].y * v[i].y + v[i].z * v[i].z + v[i].w * v[i].w;
#pragma unroll
    for (int off = 16; off > 0; off >>= 1)
        ss += __shfl_xor_sync(0xffffffffu, ss, off);

    float inv = 1.0f / fmaxf(sqrtf(ss), 1e-12f);

    union { __half2 h[8]; uint4 q[2]; } u;
#pragma unroll
    for (int i = 0; i < 4; i++) {
        u.h[2 * i]     = __float22half2_rn(make_float2(v[i].x * inv, v[i].y * inv));
        u.h[2 * i + 1] = __float22half2_rn(make_float2(v[i].z * inv, v[i].w * inv));
    }

    int kbase = lane * 16;
#pragma unroll
    for (int uu = 0; uu < 2; uu++) {
        int kin = kbase + uu * 8;
        int chunk = kin >> 6;
        int off = rowin * 128 + (kin & 63) * 2;
        int swz = off ^ ((off >> 3) & 0x70);
        *(uint4*)(img + (size_t)chunk * chunk_stride + swz) = u.q[uu];
    }
}

// ---------------------------------------------------------------------------
// Kernel 2: f16 HMMA GEMM, CTA tile 128x256 (K=512), warp tile 64x64,
// 2-stage cp.async ring, one barrier per chunk, 2 CTAs/SM.
// warp == (2 tokens, 1 video) -> two outputs per warp.
// ---------------------------------------------------------------------------
__global__ void __launch_bounds__(256, 2) gemm_kernel(
    const float* __restrict__ lsc, float* __restrict__ out) {
    extern __shared__ unsigned char smem[];
    uint32_t sbase = smem_u32(smem);

    int tid = threadIdx.x, wid = tid >> 5, lane = tid & 31;
    int mtile = blockIdx.y, npair = blockIdx.x;      // npair covers 2 ntile images
    int wm = wid >> 2, wn = wid & 3;                 // 2M x 4N

    const unsigned char* asrc = g_ncp + (size_t)mtile * AIMG;
    const unsigned char* bsrc = g_nfp + (size_t)npair * (2 * BIMG);
    const size_t ACS = (size_t)MT * AIMG;
    const size_t BCS = (size_t)NT * BIMG;

    // per-lane ldmatrix offsets (swizzle folded in)
    // A rows: wm*64 + mt*16 + (lane & 15), mt = 0..3
    uint32_t Aoff[4], Axm[4];
#pragma unroll
    for (int mt = 0; mt < 4; mt++) {
        int row = wm * 64 + mt * 16 + (lane & 15);
        Aoff[mt] = row * 128;
        Axm[mt] = (row & 7) << 4;
    }
    uint32_t kA = (lane & 16);

    // B: warp reads cols wn*64 of the 256 -> image (wn>>1), rows (wn&1)*64 + ...
    uint32_t Bimg = AIMG + (uint32_t)(wn >> 1) * BIMG;   // offset within stage
    uint32_t Boff[4], Bxm[4];
#pragma unroll
    for (int bp = 0; bp < 4; bp++) {
        int row = (wn & 1) * 64 + bp * 16 + (lane & 7) + ((lane & 16) ? 8 : 0);
        Boff[bp] = row * 128;
        Bxm[bp] = (row & 7) << 4;
    }
    uint32_t kB = (lane & 8) ? 16u : 0u;

    uint32_t acc[4][8][2];                 // [mt][n-oct][h], half2 per reg
#pragma unroll
    for (int i = 0; i < 4; i++)
#pragma unroll
        for (int j = 0; j < 8; j++) { acc[i][j][0] = 0u; acc[i][j][1] = 0u; }

    // prologue: prefetch chunk 0 (A 16KB + B 32KB contiguous)
    {
#pragma unroll
        for (int j = 0; j < 12; j++) {
            uint32_t off = tid * 16 + j * 4096;
            const unsigned char* src = (j < 4) ? asrc + off
                                               : bsrc + (off - AIMG);
            cp_async16(sbase + off, src);
        }
        cp_commit();
    }

#pragma unroll 1
    for (int c = 0; c < NCH; c++) {
        cp_wait<0>();
        __syncthreads();
        if (c + 1 < NCH) {
            int cn = c + 1;
            uint32_t dst = sbase + (cn & 1) * STAGE;
#pragma unroll
            for (int j = 0; j < 12; j++) {
                uint32_t off = tid * 16 + j * 4096;
                const unsigned char* src = (j < 4)
                    ? asrc + cn * ACS + off
                    : bsrc + cn * BCS + (off - AIMG);
                cp_async16(dst + off, src);
            }
            cp_commit();
        }

        uint32_t sa = sbase + (c & 1) * STAGE;
        uint32_t sb = sa + Bimg;

#pragma unroll
        for (int ks = 0; ks < 4; ks++) {
            uint32_t kb = ks * 32;
            uint32_t a[4][4];
#pragma unroll
            for (int mt = 0; mt < 4; mt++)
                ldm_x4(a[mt], sa + Aoff[mt] + ((kb + kA) ^ Axm[mt]));
#pragma unroll
            for (int bp = 0; bp < 4; bp++) {
                uint32_t b[4];
                ldm_x4(b, sb + Boff[bp] + ((kb + kB) ^ Bxm[bp]));
#pragma unroll
                for (int mt = 0; mt < 4; mt++) {
                    mma16816h(acc[mt][2 * bp],     a[mt], b[0], b[1]);
                    mma16816h(acc[mt][2 * bp + 1], a[mt], b[2], b[3]);
                }
            }
        }
    }

    // ---- fused epilogue ----
    // Row of acc[mt][*][h] = wm*64 + mt*16 + (lane>>2) + 8h.
    // Token tt = mt>>1. Max over 8 n-octs (64 frame cols) then quad lanes.
    float rm[4][2];
#pragma unroll
    for (int mt = 0; mt < 4; mt++)
#pragma unroll
        for (int h = 0; h < 2; h++) {
            __half2 m = __halves2half2(__ushort_as_half(0xFBFFu),
                                       __ushort_as_half(0xFBFFu));  // -65504
#pragma unroll
            for (int np = 0; np < 8; np++)
                m = __hmax2(m, *(__half2*)&acc[mt][np][h]);
            float2 f = __half22float2(m);
            rm[mt][h] = fmaxf(f.x, f.y);
        }
#pragma unroll
    for (int off = 1; off <= 2; off <<= 1) {
#pragma unroll
        for (int mt = 0; mt < 4; mt++)
#pragma unroll
            for (int h = 0; h < 2; h++)
                rm[mt][h] = fmaxf(rm[mt][h],
                                  __shfl_xor_sync(0xffffffffu, rm[mt][h], off));
    }
    float s0 = rm[0][0] + rm[0][1] + rm[1][0] + rm[1][1];   // token wm*2+0... rows 0..31
    float s1 = rm[2][0] + rm[2][1] + rm[3][0] + rm[3][1];   // rows 32..63
#pragma unroll
    for (int off = 4; off <= 16; off <<= 1) {
        s0 += __shfl_xor_sync(0xffffffffu, s0, off);
        s1 += __shfl_xor_sync(0xffffffffu, s1, off);
    }

    if (lane == 0) {
        int t0 = mtile * 4 + wm * 2;
        int v = npair * 4 + wn;
        float scale = fminf(expf(lsc[0]), 100.0f);
        float g0 = __ldg(&g_gsim[(size_t)t0 * 256 + v]);
        float g1 = __ldg(&g_gsim[(size_t)(t0 + 1) * 256 + v]);
        out[(size_t)t0 * 256 + v]       = scale * (0.7f * g0 + 0.3f * (s0 * (1.0f / 32.0f)));
        out[(size_t)(t0 + 1) * 256 + v] = scale * (0.7f * g1 + 0.3f * (s1 * (1.0f / 32.0f)));
    }
}

// ---------------------------------------------------------------------------
extern "C" void kernel_launch(void* const* d_in, const int* in_sizes, int n_in,
                              void* d_out, int out_size) {
    const float* text    = (const float*)d_in[0];
    const float* clip    = (const float*)d_in[1];
    const float* concept = (const float*)d_in[2];
    const float* frame   = (const float*)d_in[3];
    const float* lsc     = (const float*)d_in[4];
    float* out = (float*)d_out;

    cudaFuncSetAttribute(prep_kernel, cudaFuncAttributeMaxDynamicSharedMemorySize,
                         GSIM_SMEM);
    prep_kernel<<<PREP_BLOCKS + GSIM_BLOCKS, 256, GSIM_SMEM>>>(
        text, clip, concept, frame);

    cudaFuncSetAttribute(gemm_kernel, cudaFuncAttributeMaxDynamicSharedMemorySize,
                         SMEM_DYN);
    gemm_kernel<<<dim3(NT / 2, MT), 256, SMEM_DYN>>>(lsc, out);
}